// round 6
// baseline (speedup 1.0000x reference)
#include <cuda_runtime.h>

#define BB 32
#define NN 16384
#define PP 4096
#define CC 14
#define TPB 256
#define PTS 8
#define SEGS (NN / (TPB * PTS))          // 8 dist segments per batch
#define NBLK (BB * SEGS)                 // 256 blocks total (single wave, co-resident)
#define CBB 4                            // centroid blocks per batch (seg 0..3)
#define NW (TPB / 32)                    // 8 warps

typedef unsigned long long u64;

// all zero-initialized at module load; every replay restores them
__device__ unsigned g_count;
__device__ unsigned g_bcnt[BB];
__device__ float    g_sums[BB][CC * 4];
__device__ float4   g_centP[BB][CC];     // (-2cx, -2cy, -2cz, ||c||^2)
__device__ unsigned g_flag[BB];
__device__ float    g_part[NBLK];

// ---------- packed f32x2 helpers (FFMA2/FADD2 — ptxas won't emit from C++) ----------
__device__ __forceinline__ u64 pk2(float lo, float hi) {
    u64 r; asm("mov.b64 %0, {%1, %2};" : "=l"(r) : "f"(lo), "f"(hi)); return r;
}
__device__ __forceinline__ void upk2(u64 v, float& lo, float& hi) {
    asm("mov.b64 {%0, %1}, %2;" : "=f"(lo), "=f"(hi) : "l"(v));
}
__device__ __forceinline__ u64 add2(u64 a, u64 b) {
    u64 r; asm("add.rn.f32x2 %0, %1, %2;" : "=l"(r) : "l"(a), "l"(b)); return r;
}
__device__ __forceinline__ u64 mul2(u64 a, u64 b) {
    u64 r; asm("mul.rn.f32x2 %0, %1, %2;" : "=l"(r) : "l"(a), "l"(b)); return r;
}
__device__ __forceinline__ u64 fma2(u64 a, u64 b, u64 c) {
    u64 r; asm("fma.rn.f32x2 %0, %1, %2, %3;" : "=l"(r) : "l"(a), "l"(b), "l"(c)); return r;
}

__device__ __forceinline__ float smooth_l1(float x) {
    const float ax = fabsf(x);
    return (ax < 1.0f) ? (0.5f * x * x) : (ax - 0.5f);
}
__device__ __forceinline__ float sqrt_fast(float x) {
    float r; asm("sqrt.approx.f32 %0, %1;" : "=f"(r) : "f"(x)); return r;
}
__device__ __forceinline__ unsigned ld_acq(const unsigned* p) {
    unsigned v;
    asm volatile("ld.acquire.gpu.u32 %0, [%1];" : "=r"(v) : "l"(p) : "memory");
    return v;
}
__device__ __forceinline__ void st_rel(unsigned* p, unsigned v) {
    asm volatile("st.release.gpu.u32 [%0], %1;" :: "l"(p), "r"(v) : "memory");
}
__device__ __forceinline__ unsigned atom_inc_acqrel(unsigned* p) {
    unsigned old;
    asm volatile("atom.acq_rel.gpu.add.u32 %0, [%1], %2;"
                 : "=r"(old) : "l"(p), "r"(1u) : "memory");
    return old;
}

__global__ void __launch_bounds__(TPB) k_fused(
        const float* __restrict__ disp, const float* __restrict__ sub,
        const float* __restrict__ cpred, const float* __restrict__ origin,
        const int* __restrict__ tgt, float* __restrict__ out)
{
    const int bid = blockIdx.x;
    const int tid = threadIdx.x;
    const int lane = tid & 31, wid = tid >> 5;
    const int b = bid / SEGS;
    const int seg = bid % SEGS;

    __shared__ u64   redp[NW][CC * 2];   // packed cross-warp reduce (28 u64 per warp)
    __shared__ u64   finp[CC * 2];
    __shared__ float s_cgx[CC], s_cgy[CC], s_cgz[CC];
    __shared__ u64   s_cx[CC], s_cy[CC], s_cz[CC], s_cw[CC];  // splat-packed centroids
    __shared__ float wsum[NW];
    __shared__ double dsum[NW];
    __shared__ int s_lastc, s_win;

    // ====== issue ALL dist loads up front (overlaps DRAM latency with phase 1) ======
    const float* __restrict__ dp = disp + (size_t)b * NN;
    const float* __restrict__ sx = sub + (size_t)b * 3 * NN;
    const float* __restrict__ sy = sx + NN;
    const float* __restrict__ sz = sx + 2 * NN;
    const int o0 = seg * (TPB * PTS) + tid * 4;
    const int o1 = o0 + TPB * 4;

    const float4 dA = *(const float4*)(dp + o0);
    const float4 dB = *(const float4*)(dp + o1);
    const float4 xA = *(const float4*)(sx + o0);
    const float4 xB = *(const float4*)(sx + o1);
    const float4 yA = *(const float4*)(sy + o0);
    const float4 yB = *(const float4*)(sy + o1);
    const float4 zA = *(const float4*)(sz + o0);
    const float4 zB = *(const float4*)(sz + o1);

    float extra = 0.0f;   // chamfer+separation (winner-leader tid0 only)

    // ================= phase 1: centroids (seg < 4) =================
    if (seg < CBB) {
        const float* __restrict__ ox = origin + (size_t)b * 9 * PP + seg * (PP / CBB);
        const float* __restrict__ oy = ox + PP;
        const float* __restrict__ oz = ox + 2 * PP;
        const int* __restrict__ tg = tgt + (size_t)b * PP + seg * (PP / CBB);

        const int4 c4 = *(const int4*)(tg + tid * 4);
        const float4 x4 = *(const float4*)(ox + tid * 4);
        const float4 y4 = *(const float4*)(oy + tid * 4);
        const float4 z4 = *(const float4*)(oz + tid * 4);
        const int cs[4] = {c4.x, c4.y, c4.z, c4.w};
        const float px[4] = {x4.x, x4.y, x4.z, x4.w};
        const float py[4] = {y4.x, y4.y, y4.z, y4.w};
        const float pz[4] = {z4.x, z4.y, z4.z, z4.w};

        float bins[CC * 4];
        #pragma unroll
        for (int k = 0; k < CC * 4; k++) bins[k] = 0.0f;
        #pragma unroll
        for (int i = 0; i < 4; i++) {
            const int c = cs[i];
            #pragma unroll
            for (int cc = 0; cc < CC; cc++) {
                if (c == cc) {             // predicated FADDs
                    bins[cc * 4 + 0] += px[i];
                    bins[cc * 4 + 1] += py[i];
                    bins[cc * 4 + 2] += pz[i];
                    bins[cc * 4 + 3] += 1.0f;
                }
            }
        }
        // packed warp reduce: 28 f32x2 values, 5 levels
        u64 pb[CC * 2];
        #pragma unroll
        for (int k = 0; k < CC * 2; k++) pb[k] = pk2(bins[2 * k], bins[2 * k + 1]);
        #pragma unroll
        for (int off = 16; off > 0; off >>= 1) {
            #pragma unroll
            for (int k = 0; k < CC * 2; k++)
                pb[k] = add2(pb[k], __shfl_xor_sync(0xFFFFFFFFu, pb[k], off));
        }
        if (lane == 0) {
            #pragma unroll
            for (int k = 0; k < CC * 2; k++) redp[wid][k] = pb[k];
        }
        __syncthreads();
        if (tid < CC * 2) {
            u64 s = redp[0][tid];
            #pragma unroll
            for (int w = 1; w < NW; w++) s = add2(s, redp[w][tid]);
            float lo, hi;
            upk2(s, lo, hi);
            atomicAdd(&g_sums[b][2 * tid + 0], lo);
            atomicAdd(&g_sums[b][2 * tid + 1], hi);
        }
        __syncthreads();
        if (tid == 0)
            s_lastc = (atom_inc_acqrel(&g_bcnt[b]) == CBB - 1);
        __syncthreads();

        if (s_lastc) {
            __shared__ float fin[CC * 4];
            if (tid < CC * 4) {
                fin[tid] = g_sums[b][tid];
                g_sums[b][tid] = 0.0f;       // reset for next replay
            }
            __syncthreads();
            if (tid < CC) {
                const float cnt = fmaxf(fin[tid * 4 + 3], 1.0f);
                const float inv = 1.0f / cnt;
                const float x = fin[tid * 4 + 0] * inv;
                const float y = fin[tid * 4 + 1] * inv;
                const float z = fin[tid * 4 + 2] * inv;
                s_cgx[tid] = x; s_cgy[tid] = y; s_cgz[tid] = z;
                g_centP[b][tid] = make_float4(-2.0f * x, -2.0f * y, -2.0f * z,
                                              fmaf(x, x, fmaf(y, y, z * z)));
            }
            __syncthreads();
            if (tid == 0) {
                g_bcnt[b] = 0;
                st_rel(&g_flag[b], 1u);      // release dist blocks ASAP
            }
            // chamfer + separation overlaps pollers' dist start
            if (tid < 32) {
                float local = 0.0f;
                if (tid < CC) {
                    const float* __restrict__ cp = cpred + (size_t)b * 3 * CC;
                    const float qx = cp[tid], qy = cp[CC + tid], qz = cp[2 * CC + tid];
                    float rmin = 3.4e38f, m1 = 3.4e38f, m2 = 3.4e38f;
                    #pragma unroll
                    for (int j = 0; j < CC; j++) {
                        const float dx = qx - s_cgx[j], dy = qy - s_cgy[j], dz = qz - s_cgz[j];
                        const float d2 = fmaf(dx, dx, fmaf(dy, dy, dz * dz));
                        rmin = fminf(rmin, d2);
                        const float dd = sqrt_fast(d2);
                        if (dd < m1) { m2 = m1; m1 = dd; }
                        else if (dd < m2) { m2 = dd; }
                    }
                    const float gx = s_cgx[tid], gy = s_cgy[tid], gz = s_cgz[tid];
                    float cmin = 3.4e38f;
                    #pragma unroll
                    for (int i = 0; i < CC; i++) {
                        const float dx = cp[i] - gx, dy = cp[CC + i] - gy, dz = cp[2 * CC + i] - gz;
                        cmin = fminf(cmin, fmaf(dx, dx, fmaf(dy, dy, dz * dz)));
                    }
                    local = rmin + cmin + 0.1f * (m1 / m2);
                }
                #pragma unroll
                for (int off = 16; off > 0; off >>= 1)
                    local += __shfl_xor_sync(0xFFFFFFFFu, local, off);
                if (tid == 0) extra = local;
            }
        }
    }

    // ================= phase 2: distance loss (all blocks) =================
    {
        // pack points into f32x2 pairs (adjacent regs -> near-free movs)
        const u64 Xp[4] = {pk2(xA.x, xA.y), pk2(xA.z, xA.w), pk2(xB.x, xB.y), pk2(xB.z, xB.w)};
        const u64 Yp[4] = {pk2(yA.x, yA.y), pk2(yA.z, yA.w), pk2(yB.x, yB.y), pk2(yB.z, yB.w)};
        const u64 Zp[4] = {pk2(zA.x, zA.y), pk2(zA.z, zA.w), pk2(zB.x, zB.y), pk2(zB.z, zB.w)};
        const float ds[8] = {dA.x, dA.y, dA.z, dA.w, dB.x, dB.y, dB.z, dB.w};

        float pn[8];
        #pragma unroll
        for (int j = 0; j < 4; j++) {
            const u64 p = fma2(Xp[j], Xp[j], fma2(Yp[j], Yp[j], mul2(Zp[j], Zp[j])));
            upk2(p, pn[2 * j], pn[2 * j + 1]);
        }

        // acquire-poll + fetch + splat-pack centroids (lanes 0..13 of warp 0)
        if (tid < CC) {
            while (ld_acq(&g_flag[b]) == 0u) __nanosleep(32);
            const float4 cp = g_centP[b][tid];
            s_cx[tid] = pk2(cp.x, cp.x);
            s_cy[tid] = pk2(cp.y, cp.y);
            s_cz[tid] = pk2(cp.z, cp.z);
            s_cw[tid] = pk2(cp.w, cp.w);
        }
        __syncthreads();

        float tmin[8];
        #pragma unroll
        for (int k = 0; k < 8; k++) tmin[k] = 3.4e38f;
        #pragma unroll
        for (int c = 0; c < CC; c++) {
            const u64 cx = s_cx[c], cy = s_cy[c], cz = s_cz[c], cw = s_cw[c];
            #pragma unroll
            for (int j = 0; j < 4; j++) {
                const u64 t = fma2(Xp[j], cx, fma2(Yp[j], cy, fma2(Zp[j], cz, cw)));
                float t0, t1;
                upk2(t, t0, t1);
                tmin[2 * j]     = fminf(tmin[2 * j], t0);
                tmin[2 * j + 1] = fminf(tmin[2 * j + 1], t1);
            }
        }
        float local = 0.0f;
        #pragma unroll
        for (int k = 0; k < 8; k++) {
            const float d2 = fmaxf(pn[k] + tmin[k], 0.0f);
            local += smooth_l1(ds[k] - sqrt_fast(d2));
        }

        #pragma unroll
        for (int off = 16; off > 0; off >>= 1)
            local += __shfl_xor_sync(0xFFFFFFFFu, local, off);
        if (lane == 0) wsum[wid] = local;
        __syncthreads();

        if (tid == 0) {
            float v = extra;
            #pragma unroll
            for (int w = 0; w < NW; w++) v += wsum[w];
            g_part[bid] = v;                                   // plain store
            s_win = (atom_inc_acqrel(&g_count) == NBLK - 1);   // release publishes it
        }
        __syncthreads();

        if (s_win) {
            double dv = (double)g_part[tid];
            #pragma unroll
            for (int off = 16; off > 0; off >>= 1)
                dv += __shfl_xor_sync(0xFFFFFFFFu, dv, off);
            if (lane == 0) dsum[wid] = dv;
            __syncthreads();
            if (tid == 0) {
                double tot = 0.0;
                #pragma unroll
                for (int w = 0; w < NW; w++) tot += dsum[w];
                out[0] = (float)tot;
                g_count = 0;
            }
            if (tid < BB) g_flag[tid] = 0;
        }
    }
}

extern "C" void kernel_launch(void* const* d_in, const int* in_sizes, int n_in,
                              void* d_out, int out_size) {
    const float* disp   = (const float*)d_in[0];       // [B, N]
    const float* sub    = (const float*)d_in[1];       // [B, 3, N]
    const float* cpred  = (const float*)d_in[2];       // [B, 3, C]
    const float* origin = (const float*)d_in[3];       // [B, 9, P]
    const int*   tg     = (const int*)d_in[4];         // [B, P]
    float* out = (float*)d_out;

    k_fused<<<NBLK, TPB>>>(disp, sub, cpred, origin, tg, out);
}

// round 7
// speedup vs baseline: 1.4088x; 1.4088x over previous
#include <cuda_runtime.h>

#define BB 32
#define NN 16384
#define PP 4096
#define CC 14
#define TPB 256
#define PTS 8
#define SEGS (NN / (TPB * PTS))          // 8 dist segments per batch
#define NBLK (BB * SEGS)                 // 256 blocks total (single wave, co-resident)
#define CBB SEGS                         // ALL 8 blocks per batch do centroid work
#define NW (TPB / 32)                    // 8 warps

// all zero-initialized at module load; every replay restores them
__device__ unsigned g_count;
__device__ unsigned g_bcnt[BB];
__device__ float    g_sums[BB][CC * 4];
__device__ float4   g_centP[BB][CC];     // (-2cx, -2cy, -2cz, ||c||^2)
__device__ unsigned g_flag[BB];
__device__ float    g_part[NBLK];

__device__ __forceinline__ float smooth_l1(float x) {
    const float ax = fabsf(x);
    return (ax < 1.0f) ? (0.5f * x * x) : (ax - 0.5f);
}
__device__ __forceinline__ float sqrt_fast(float x) {
    float r; asm("sqrt.approx.f32 %0, %1;" : "=f"(r) : "f"(x)); return r;
}
__device__ __forceinline__ unsigned ld_acq(const unsigned* p) {
    unsigned v;
    asm volatile("ld.acquire.gpu.u32 %0, [%1];" : "=r"(v) : "l"(p) : "memory");
    return v;
}
__device__ __forceinline__ void st_rel(unsigned* p, unsigned v) {
    asm volatile("st.release.gpu.u32 [%0], %1;" :: "l"(p), "r"(v) : "memory");
}
__device__ __forceinline__ unsigned atom_inc_acqrel(unsigned* p) {
    unsigned old;
    asm volatile("atom.acq_rel.gpu.add.u32 %0, [%1], %2;"
                 : "=r"(old) : "l"(p), "r"(1u) : "memory");
    return old;
}

__global__ void __launch_bounds__(TPB) k_fused(
        const float* __restrict__ disp, const float* __restrict__ sub,
        const float* __restrict__ cpred, const float* __restrict__ origin,
        const int* __restrict__ tgt, float* __restrict__ out)
{
    const int bid = blockIdx.x;
    const int tid = threadIdx.x;
    const int lane = tid & 31, wid = tid >> 5;
    const int b = bid / SEGS;
    const int seg = bid % SEGS;

    __shared__ float red[NW][CC * 4];
    __shared__ float s_cgx[CC], s_cgy[CC], s_cgz[CC];
    __shared__ float4 s_c[CC];
    __shared__ float wsum[NW];
    __shared__ double dsum[NW];
    __shared__ int s_lastc, s_win;

    float extra = 0.0f;   // chamfer+separation (winner-block tid0 only)

    // ================= phase 1: centroids (ALL blocks, 2 pts/thread) =================
    {
        const int base = seg * (PP / CBB);            // 512 points per block
        const float* __restrict__ ox = origin + (size_t)b * 9 * PP + base;
        const float* __restrict__ oy = ox + PP;
        const float* __restrict__ oz = ox + 2 * PP;
        const int* __restrict__ tg = tgt + (size_t)b * PP + base;

        const int2 c2   = *(const int2*)(tg + tid * 2);
        const float2 x2 = *(const float2*)(ox + tid * 2);
        const float2 y2 = *(const float2*)(oy + tid * 2);
        const float2 z2 = *(const float2*)(oz + tid * 2);
        const int cs[2] = {c2.x, c2.y};
        const float px[2] = {x2.x, x2.y};
        const float py[2] = {y2.x, y2.y};
        const float pz[2] = {z2.x, z2.y};

        float bins[CC * 4];
        #pragma unroll
        for (int k = 0; k < CC * 4; k++) bins[k] = 0.0f;
        #pragma unroll
        for (int i = 0; i < 2; i++) {
            const int c = cs[i];
            #pragma unroll
            for (int cc = 0; cc < CC; cc++) {
                if (c == cc) {             // predicated FADDs
                    bins[cc * 4 + 0] += px[i];
                    bins[cc * 4 + 1] += py[i];
                    bins[cc * 4 + 2] += pz[i];
                    bins[cc * 4 + 3] += 1.0f;
                }
            }
        }
        #pragma unroll
        for (int k = 0; k < CC * 4; k++) {
            #pragma unroll
            for (int off = 16; off > 0; off >>= 1)
                bins[k] += __shfl_xor_sync(0xFFFFFFFFu, bins[k], off);
        }
        if (lane == 0) {
            #pragma unroll
            for (int k = 0; k < CC * 4; k++) red[wid][k] = bins[k];
        }
        __syncthreads();
        if (tid < CC * 4) {
            float s = 0.0f;
            #pragma unroll
            for (int w = 0; w < NW; w++) s += red[w][tid];
            atomicAdd(&g_sums[b][tid], s);   // relaxed; published by acq_rel below
        }
        __syncthreads();
        if (tid == 0)
            s_lastc = (atom_inc_acqrel(&g_bcnt[b]) == CBB - 1);
        __syncthreads();

        if (s_lastc) {
            __shared__ float fin[CC * 4];
            if (tid < CC * 4) {
                fin[tid] = g_sums[b][tid];
                g_sums[b][tid] = 0.0f;       // reset for next replay
            }
            __syncthreads();
            if (tid < CC) {
                const float cnt = fmaxf(fin[tid * 4 + 3], 1.0f);
                const float inv = 1.0f / cnt;
                const float x = fin[tid * 4 + 0] * inv;
                const float y = fin[tid * 4 + 1] * inv;
                const float z = fin[tid * 4 + 2] * inv;
                s_cgx[tid] = x; s_cgy[tid] = y; s_cgz[tid] = z;
                g_centP[b][tid] = make_float4(-2.0f * x, -2.0f * y, -2.0f * z,
                                              fmaf(x, x, fmaf(y, y, z * z)));
            }
            __syncthreads();
            if (tid == 0) {
                g_bcnt[b] = 0;
                st_rel(&g_flag[b], 1u);      // release dist blocks ASAP
            }
            // chamfer + separation overlaps pollers' dist start
            if (tid < 32) {
                float local = 0.0f;
                if (tid < CC) {
                    const float* __restrict__ cp = cpred + (size_t)b * 3 * CC;
                    const float qx = cp[tid], qy = cp[CC + tid], qz = cp[2 * CC + tid];
                    float rmin = 3.4e38f, m1 = 3.4e38f, m2 = 3.4e38f;
                    #pragma unroll
                    for (int j = 0; j < CC; j++) {
                        const float dx = qx - s_cgx[j], dy = qy - s_cgy[j], dz = qz - s_cgz[j];
                        const float d2 = fmaf(dx, dx, fmaf(dy, dy, dz * dz));
                        rmin = fminf(rmin, d2);
                        const float dd = sqrt_fast(d2);
                        if (dd < m1) { m2 = m1; m1 = dd; }
                        else if (dd < m2) { m2 = dd; }
                    }
                    const float gx = s_cgx[tid], gy = s_cgy[tid], gz = s_cgz[tid];
                    float cmin = 3.4e38f;
                    #pragma unroll
                    for (int i = 0; i < CC; i++) {
                        const float dx = cp[i] - gx, dy = cp[CC + i] - gy, dz = cp[2 * CC + i] - gz;
                        cmin = fminf(cmin, fmaf(dx, dx, fmaf(dy, dy, dz * dz)));
                    }
                    local = rmin + cmin + 0.1f * (m1 / m2);
                }
                #pragma unroll
                for (int off = 16; off > 0; off >>= 1)
                    local += __shfl_xor_sync(0xFFFFFFFFu, local, off);
                if (tid == 0) extra = local;
            }
        }
    }

    // ================= phase 2: distance loss (all blocks) =================
    {
        const float* __restrict__ dp = disp + (size_t)b * NN;
        const float* __restrict__ sx = sub + (size_t)b * 3 * NN;
        const float* __restrict__ sy = sx + NN;
        const float* __restrict__ sz = sx + 2 * NN;
        const int o0 = seg * (TPB * PTS) + tid * 4;
        const int o1 = o0 + TPB * 4;

        // issue all loads + ||p||^2 BEFORE the spin (overlaps winner's finalize)
        const float4 dA = *(const float4*)(dp + o0);
        const float4 dB = *(const float4*)(dp + o1);
        const float4 xA = *(const float4*)(sx + o0);
        const float4 xB = *(const float4*)(sx + o1);
        const float4 yA = *(const float4*)(sy + o0);
        const float4 yB = *(const float4*)(sy + o1);
        const float4 zA = *(const float4*)(sz + o0);
        const float4 zB = *(const float4*)(sz + o1);

        const float xs[8] = {xA.x, xA.y, xA.z, xA.w, xB.x, xB.y, xB.z, xB.w};
        const float ys[8] = {yA.x, yA.y, yA.z, yA.w, yB.x, yB.y, yB.z, yB.w};
        const float zs[8] = {zA.x, zA.y, zA.z, zA.w, zB.x, zB.y, zB.z, zB.w};
        const float ds[8] = {dA.x, dA.y, dA.z, dA.w, dB.x, dB.y, dB.z, dB.w};
        float pn[8];
        #pragma unroll
        for (int k = 0; k < 8; k++)
            pn[k] = fmaf(xs[k], xs[k], fmaf(ys[k], ys[k], zs[k] * zs[k]));

        // acquire-poll + fetch packed centroids (lanes 0..13 of warp 0)
        if (tid < CC) {
            while (ld_acq(&g_flag[b]) == 0u) __nanosleep(32);
            s_c[tid] = g_centP[b][tid];
        }
        __syncthreads();

        float tmin[8];
        #pragma unroll
        for (int k = 0; k < 8; k++) tmin[k] = 3.4e38f;
        #pragma unroll
        for (int c = 0; c < CC; c++) {
            const float4 cp = s_c[c];
            #pragma unroll
            for (int k = 0; k < 8; k++) {
                const float t = fmaf(xs[k], cp.x, fmaf(ys[k], cp.y, fmaf(zs[k], cp.z, cp.w)));
                tmin[k] = fminf(tmin[k], t);
            }
        }
        float local = 0.0f;
        #pragma unroll
        for (int k = 0; k < 8; k++) {
            const float d2 = fmaxf(pn[k] + tmin[k], 0.0f);
            local += smooth_l1(ds[k] - sqrt_fast(d2));
        }

        #pragma unroll
        for (int off = 16; off > 0; off >>= 1)
            local += __shfl_xor_sync(0xFFFFFFFFu, local, off);
        if (lane == 0) wsum[wid] = local;
        __syncthreads();

        if (tid == 0) {
            float v = extra;
            #pragma unroll
            for (int w = 0; w < NW; w++) v += wsum[w];
            g_part[bid] = v;                                   // plain store
            s_win = (atom_inc_acqrel(&g_count) == NBLK - 1);   // release publishes it
        }
        __syncthreads();

        if (s_win) {
            double dv = (double)g_part[tid];
            #pragma unroll
            for (int off = 16; off > 0; off >>= 1)
                dv += __shfl_xor_sync(0xFFFFFFFFu, dv, off);
            if (lane == 0) dsum[wid] = dv;
            __syncthreads();
            if (tid == 0) {
                double tot = 0.0;
                #pragma unroll
                for (int w = 0; w < NW; w++) tot += dsum[w];
                out[0] = (float)tot;
                g_count = 0;
            }
            if (tid < BB) g_flag[tid] = 0;
        }
    }
}

extern "C" void kernel_launch(void* const* d_in, const int* in_sizes, int n_in,
                              void* d_out, int out_size) {
    const float* disp   = (const float*)d_in[0];       // [B, N]
    const float* sub    = (const float*)d_in[1];       // [B, 3, N]
    const float* cpred  = (const float*)d_in[2];       // [B, 3, C]
    const float* origin = (const float*)d_in[3];       // [B, 9, P]
    const int*   tg     = (const int*)d_in[4];         // [B, P]
    float* out = (float*)d_out;

    k_fused<<<NBLK, TPB>>>(disp, sub, cpred, origin, tg, out);
}

// round 8
// speedup vs baseline: 1.5589x; 1.1065x over previous
#include <cuda_runtime.h>

#define BB 32
#define NN 16384
#define PP 4096
#define CC 14
#define TPB 256
#define PTS 8
#define SEGS (NN / (TPB * PTS))          // 8 dist segments per batch
#define NBLK (BB * SEGS)                 // 256 blocks total (single wave, co-resident)
#define CBB SEGS                         // ALL 8 blocks per batch do centroid work
#define NW (TPB / 32)                    // 8 warps

// all zero-initialized at module load; every replay restores them
__device__ unsigned g_count;
__device__ unsigned g_bcnt[BB];
__device__ float    g_sums[BB][CC * 4];  // float4-aligned per class
__device__ float4   g_centP[BB][CC];     // (-2cx, -2cy, -2cz, ||c||^2)
__device__ unsigned g_flag[BB];
__device__ float    g_part[NBLK];

__device__ __forceinline__ float smooth_l1(float x) {
    const float ax = fabsf(x);
    return (ax < 1.0f) ? (0.5f * x * x) : (ax - 0.5f);
}
__device__ __forceinline__ float sqrt_fast(float x) {
    float r; asm("sqrt.approx.f32 %0, %1;" : "=f"(r) : "f"(x)); return r;
}
__device__ __forceinline__ unsigned ld_acq(const unsigned* p) {
    unsigned v;
    asm volatile("ld.acquire.gpu.u32 %0, [%1];" : "=r"(v) : "l"(p) : "memory");
    return v;
}
__device__ __forceinline__ void st_rel(unsigned* p, unsigned v) {
    asm volatile("st.release.gpu.u32 [%0], %1;" :: "l"(p), "r"(v) : "memory");
}
__device__ __forceinline__ unsigned atom_inc_acqrel(unsigned* p) {
    unsigned old;
    asm volatile("atom.acq_rel.gpu.add.u32 %0, [%1], %2;"
                 : "=r"(old) : "l"(p), "r"(1u) : "memory");
    return old;
}

__global__ void __launch_bounds__(TPB) k_fused(
        const float* __restrict__ disp, const float* __restrict__ sub,
        const float* __restrict__ cpred, const float* __restrict__ origin,
        const int* __restrict__ tgt, float* __restrict__ out)
{
    const int bid = blockIdx.x;
    const int tid = threadIdx.x;
    const int lane = tid & 31, wid = tid >> 5;
    const int b = bid / SEGS;
    const int seg = bid % SEGS;

    __shared__ float red[NW][64];
    __shared__ float s_cgx[CC], s_cgy[CC], s_cgz[CC];
    __shared__ float4 s_c[CC];
    __shared__ float wsum[NW];
    __shared__ double dsum[NW];
    __shared__ int s_lastc, s_win;

    float extra = 0.0f;   // chamfer+separation (winner-block tid0 only)

    // ================= phase 1: centroids (ALL blocks, 2 pts/thread) =================
    {
        const int base = seg * (PP / CBB);            // 512 points per block
        const float* __restrict__ ox = origin + (size_t)b * 9 * PP + base;
        const float* __restrict__ oy = ox + PP;
        const float* __restrict__ oz = ox + 2 * PP;
        const int* __restrict__ tg = tgt + (size_t)b * PP + base;

        const int2 c2   = *(const int2*)(tg + tid * 2);
        const float2 x2 = *(const float2*)(ox + tid * 2);
        const float2 y2 = *(const float2*)(oy + tid * 2);
        const float2 z2 = *(const float2*)(oz + tid * 2);
        const int cs[2] = {c2.x, c2.y};
        const float px[2] = {x2.x, x2.y};
        const float py[2] = {y2.x, y2.y};
        const float pz[2] = {z2.x, z2.y};

        // padded bins: [class*4 + comp], 56..63 stay zero
        float v[64];
        #pragma unroll
        for (int k = 0; k < 64; k++) v[k] = 0.0f;
        #pragma unroll
        for (int i = 0; i < 2; i++) {
            const int c = cs[i];
            #pragma unroll
            for (int cc = 0; cc < CC; cc++) {
                if (c == cc) {             // predicated FADDs
                    v[cc * 4 + 0] += px[i];
                    v[cc * 4 + 1] += py[i];
                    v[cc * 4 + 2] += pz[i];
                    v[cc * 4 + 3] += 1.0f;
                }
            }
        }

        // reduce-scatter: 5 exchange levels; lane l ends owning totals 2l, 2l+1
        #pragma unroll
        for (int off = 16, cnt = 64; off >= 1; off >>= 1, cnt >>= 1) {
            const int half = cnt >> 1;
            const bool hi = (lane & off) != 0;
            #pragma unroll
            for (int i = 0; i < 32; i++) {   // bounded by max half; guarded below
                if (i < half) {
                    const float send = hi ? v[i] : v[i + half];
                    const float recv = __shfl_xor_sync(0xFFFFFFFFu, send, off);
                    const float keep = hi ? v[i + half] : v[i];
                    v[i] = keep + recv;
                }
            }
        }
        // lane owns padded bins 2*lane and 2*lane+1
        if (lane < 28) {
            red[wid][2 * lane]     = v[0];
            red[wid][2 * lane + 1] = v[1];
        }
        __syncthreads();
        if (tid < CC * 4) {
            float s = 0.0f;
            #pragma unroll
            for (int w = 0; w < NW; w++) s += red[w][tid];
            atomicAdd(&g_sums[b][tid], s);   // relaxed; published by acq_rel below
        }
        __syncthreads();
        if (tid == 0)
            s_lastc = (atom_inc_acqrel(&g_bcnt[b]) == CBB - 1);
        __syncthreads();

        if (s_lastc) {
            if (tid < CC) {
                const float4 f = *(const float4*)&g_sums[b][tid * 4];
                *(float4*)&g_sums[b][tid * 4] = make_float4(0.f, 0.f, 0.f, 0.f);  // reset
                const float inv = 1.0f / fmaxf(f.w, 1.0f);
                const float x = f.x * inv, y = f.y * inv, z = f.z * inv;
                s_cgx[tid] = x; s_cgy[tid] = y; s_cgz[tid] = z;
                g_centP[b][tid] = make_float4(-2.0f * x, -2.0f * y, -2.0f * z,
                                              fmaf(x, x, fmaf(y, y, z * z)));
            }
            __syncthreads();
            if (tid == 0) {
                g_bcnt[b] = 0;
                st_rel(&g_flag[b], 1u);      // release dist blocks ASAP
            }
            // chamfer + separation overlaps pollers' dist start
            if (tid < 32) {
                float local = 0.0f;
                if (tid < CC) {
                    const float* __restrict__ cp = cpred + (size_t)b * 3 * CC;
                    const float qx = cp[tid], qy = cp[CC + tid], qz = cp[2 * CC + tid];
                    float rmin = 3.4e38f, m1 = 3.4e38f, m2 = 3.4e38f;
                    #pragma unroll
                    for (int j = 0; j < CC; j++) {
                        const float dx = qx - s_cgx[j], dy = qy - s_cgy[j], dz = qz - s_cgz[j];
                        const float d2 = fmaf(dx, dx, fmaf(dy, dy, dz * dz));
                        rmin = fminf(rmin, d2);
                        const float dd = sqrt_fast(d2);
                        if (dd < m1) { m2 = m1; m1 = dd; }
                        else if (dd < m2) { m2 = dd; }
                    }
                    const float gx = s_cgx[tid], gy = s_cgy[tid], gz = s_cgz[tid];
                    float cmin = 3.4e38f;
                    #pragma unroll
                    for (int i = 0; i < CC; i++) {
                        const float dx = cp[i] - gx, dy = cp[CC + i] - gy, dz = cp[2 * CC + i] - gz;
                        cmin = fminf(cmin, fmaf(dx, dx, fmaf(dy, dy, dz * dz)));
                    }
                    local = rmin + cmin + 0.1f * (m1 / m2);
                }
                #pragma unroll
                for (int off = 16; off > 0; off >>= 1)
                    local += __shfl_xor_sync(0xFFFFFFFFu, local, off);
                if (tid == 0) extra = local;
            }
        }
    }

    // ================= phase 2: distance loss (all blocks) =================
    {
        const float* __restrict__ dp = disp + (size_t)b * NN;
        const float* __restrict__ sx = sub + (size_t)b * 3 * NN;
        const float* __restrict__ sy = sx + NN;
        const float* __restrict__ sz = sx + 2 * NN;
        const int o0 = seg * (TPB * PTS) + tid * 4;
        const int o1 = o0 + TPB * 4;

        // issue all loads + ||p||^2 BEFORE the spin (overlaps winner's finalize)
        const float4 dA = *(const float4*)(dp + o0);
        const float4 dB = *(const float4*)(dp + o1);
        const float4 xA = *(const float4*)(sx + o0);
        const float4 xB = *(const float4*)(sx + o1);
        const float4 yA = *(const float4*)(sy + o0);
        const float4 yB = *(const float4*)(sy + o1);
        const float4 zA = *(const float4*)(sz + o0);
        const float4 zB = *(const float4*)(sz + o1);

        const float xs[8] = {xA.x, xA.y, xA.z, xA.w, xB.x, xB.y, xB.z, xB.w};
        const float ys[8] = {yA.x, yA.y, yA.z, yA.w, yB.x, yB.y, yB.z, yB.w};
        const float zs[8] = {zA.x, zA.y, zA.z, zA.w, zB.x, zB.y, zB.z, zB.w};
        const float ds[8] = {dA.x, dA.y, dA.z, dA.w, dB.x, dB.y, dB.z, dB.w};
        float pn[8];
        #pragma unroll
        for (int k = 0; k < 8; k++)
            pn[k] = fmaf(xs[k], xs[k], fmaf(ys[k], ys[k], zs[k] * zs[k]));

        // acquire-poll + fetch packed centroids (lanes 0..13 of warp 0)
        if (tid < CC) {
            while (ld_acq(&g_flag[b]) == 0u) __nanosleep(32);
            s_c[tid] = g_centP[b][tid];
        }
        __syncthreads();

        float tmin[8];
        #pragma unroll
        for (int k = 0; k < 8; k++) tmin[k] = 3.4e38f;
        #pragma unroll
        for (int c = 0; c < CC; c++) {
            const float4 cp = s_c[c];
            #pragma unroll
            for (int k = 0; k < 8; k++) {
                const float t = fmaf(xs[k], cp.x, fmaf(ys[k], cp.y, fmaf(zs[k], cp.z, cp.w)));
                tmin[k] = fminf(tmin[k], t);
            }
        }
        float local = 0.0f;
        #pragma unroll
        for (int k = 0; k < 8; k++) {
            const float d2 = fmaxf(pn[k] + tmin[k], 0.0f);
            local += smooth_l1(ds[k] - sqrt_fast(d2));
        }

        #pragma unroll
        for (int off = 16; off > 0; off >>= 1)
            local += __shfl_xor_sync(0xFFFFFFFFu, local, off);
        if (lane == 0) wsum[wid] = local;
        __syncthreads();

        if (tid == 0) {
            float v2 = extra;
            #pragma unroll
            for (int w = 0; w < NW; w++) v2 += wsum[w];
            g_part[bid] = v2;                                  // plain store
            s_win = (atom_inc_acqrel(&g_count) == NBLK - 1);   // release publishes it
        }
        __syncthreads();

        if (s_win) {
            double dv = (double)g_part[tid];
            #pragma unroll
            for (int off = 16; off > 0; off >>= 1)
                dv += __shfl_xor_sync(0xFFFFFFFFu, dv, off);
            if (lane == 0) dsum[wid] = dv;
            __syncthreads();
            if (tid == 0) {
                double tot = 0.0;
                #pragma unroll
                for (int w = 0; w < NW; w++) tot += dsum[w];
                out[0] = (float)tot;
                g_count = 0;
            }
            if (tid < BB) g_flag[tid] = 0;
        }
    }
}

extern "C" void kernel_launch(void* const* d_in, const int* in_sizes, int n_in,
                              void* d_out, int out_size) {
    const float* disp   = (const float*)d_in[0];       // [B, N]
    const float* sub    = (const float*)d_in[1];       // [B, 3, N]
    const float* cpred  = (const float*)d_in[2];       // [B, 3, C]
    const float* origin = (const float*)d_in[3];       // [B, 9, P]
    const int*   tg     = (const int*)d_in[4];         // [B, P]
    float* out = (float*)d_out;

    k_fused<<<NBLK, TPB>>>(disp, sub, cpred, origin, tg, out);
}